// round 17
// baseline (speedup 1.0000x reference)
#include <cuda_runtime.h>
#include <cuda_bf16.h>
#include <cuda_fp16.h>

#define NN   100000
#define EE   1600000
#define RR   500
#define DDIM 128
#define HH   8
#define DHH  16
#define DFFN 512
#define HOPS 5
#define ALPHA 0.15f
#define SLOPE 0.2f
#define LNEPS 1e-5f

#define SCAN_B 256
#define NBLK ((NN + SCAN_B - 1) / SCAN_B)   // 391

// ---------------- scratch (static device globals; no allocation) -------------
__device__ float g_h[NN * DDIM];        // LN1 output
__device__ float g_fA[NN * DDIM];       // final hop output (fp32)
__device__ __nv_bfloat16 g_f0h[NN * DDIM];  // feat0 bf16 (hop-0 input + anchor)
__device__ __nv_bfloat16 g_hA[NN * DDIM];   // bf16 ping
__device__ __nv_bfloat16 g_hB[NN * DDIM];   // bf16 pong
__device__ __half g_eh[NN * HH];        // fp16 score parts
__device__ __half g_et[NN * HH];
__device__ __half g_er[RR * HH];
__device__ __half g_a[EE * HH];         // UNnormalized exp scores (fp16)
__device__ float g_inv[NN * HH];        // 1/softmax-sum per (node, head)
__device__ int   g_deg[NN];
__device__ int   g_rowptr[NN + 1];
__device__ int   g_cursor[NN];
__device__ int   g_part[512];           // scan partials
__device__ int   g_srcs[EE];            // src, sorted by dst
__device__ int   g_ets[EE];             // e_type, sorted by dst
// fp16 weights, k-pair packed: Wp[k/2][c] = {W[2k'][c], W[2k'+1][c]}
__device__ unsigned g_Wenth[(DDIM / 2) * DDIM];   // 8192
__device__ unsigned g_W1h[(DDIM / 2) * DFFN];     // 32768
__device__ unsigned g_W2h[(DFFN / 2) * DDIM];     // 32768

// ---------------- mma helper (fp16 m16n8k16, fp32 accum) ---------------------
__device__ __forceinline__ void mma_f16(float c[4],
    unsigned a0, unsigned a1, unsigned a2, unsigned a3,
    unsigned b0, unsigned b1)
{
    asm volatile(
        "mma.sync.aligned.m16n8k16.row.col.f32.f16.f16.f32 "
        "{%0,%1,%2,%3}, {%4,%5,%6,%7}, {%8,%9}, {%0,%1,%2,%3};"
        : "+f"(c[0]), "+f"(c[1]), "+f"(c[2]), "+f"(c[3])
        : "r"(a0), "r"(a1), "r"(a2), "r"(a3), "r"(b0), "r"(b1));
}

__device__ __forceinline__ unsigned packh2(float lo, float hi) {
    __half2 h = __floats2half2_rn(lo, hi);
    return *(unsigned*)&h;
}

// unpack a 16B row of 8 halves to floats
__device__ __forceinline__ void unp8(uint4 v, float* o) {
    __half2* hp = (__half2*)&v;
    float2 a = __half22float2(hp[0]), b = __half22float2(hp[1]);
    float2 c = __half22float2(hp[2]), d = __half22float2(hp[3]);
    o[0]=a.x; o[1]=a.y; o[2]=b.x; o[3]=b.y;
    o[4]=c.x; o[5]=c.y; o[6]=d.x; o[7]=d.y;
}

// ---------------- K0: convert + k-pair-pack all weights to fp16 --------------
#define CVT_W0 ((DDIM / 2) * DDIM)                 // 8192
#define CVT_W1 ((DDIM / 2) * DFFN)                 // 32768
#define CVT_W2 ((DFFN / 2) * DDIM)                 // 32768
#define CVT_TOTAL (CVT_W0 + CVT_W1 + CVT_W2)       // 73728
__global__ void k_cvt(const float* __restrict__ Went,
                      const float* __restrict__ W1,
                      const float* __restrict__ W2)
{
    int i = blockIdx.x * blockDim.x + threadIdx.x;
    if (i < CVT_W0) {
        int k2 = i >> 7, c = i & 127;
        g_Wenth[i] = packh2(Went[(2 * k2) * 128 + c], Went[(2 * k2 + 1) * 128 + c]);
    } else if (i < CVT_W0 + CVT_W1) {
        int j = i - CVT_W0;
        int k2 = j >> 9, c = j & 511;
        g_W1h[j] = packh2(W1[(2 * k2) * 512 + c], W1[(2 * k2 + 1) * 512 + c]);
    } else if (i < CVT_TOTAL) {
        int j = i - CVT_W0 - CVT_W1;
        int k2 = j >> 7, c = j & 127;
        g_W2h[j] = packh2(W2[(2 * k2) * 128 + c], W2[(2 * k2 + 1) * 128 + c]);
    }
}

// ---------------- K1: LN1 (gmem-direct) + feat GEMM + eh/et ------------------
// smem: yh half 64*132 = 16896 B.
__global__ void __launch_bounds__(256) k_ln1_feat(
    const float* __restrict__ ent, const float* __restrict__ g1,
    const float* __restrict__ b1,
    const float* __restrict__ ah, const float* __restrict__ at)
{
    extern __shared__ float smem_[];
    __half* yh = (__half*)smem_;              // 64*132 half LN output
    const int n0 = blockIdx.x * 64;
    const int tid = threadIdx.x;
    const int wid = tid >> 5, lane = tid & 31;
    const int group = lane >> 2, tig = lane & 3;

    #pragma unroll
    for (int rr = 0; rr < 8; rr++) {
        int r = wid * 8 + rr;
        int gr = min(n0 + r, NN - 1);
        float x[4];
        float s = 0.f, s2 = 0.f;
        #pragma unroll
        for (int k = 0; k < 4; k++) {
            x[k] = __ldg(&ent[gr * 128 + lane + 32 * k]);
            s += x[k]; s2 += x[k] * x[k];
        }
        #pragma unroll
        for (int o = 16; o; o >>= 1) {
            s  += __shfl_xor_sync(0xffffffffu, s, o);
            s2 += __shfl_xor_sync(0xffffffffu, s2, o);
        }
        float mu  = s * (1.f / 128.f);
        float inv = rsqrtf(s2 * (1.f / 128.f) - mu * mu + LNEPS);
        #pragma unroll
        for (int k = 0; k < 4; k++) {
            int c = lane + 32 * k;
            float y = (x[k] - mu) * inv * g1[c] + b1[c];
            yh[r * 132 + c] = __float2half(y);
            if (n0 + r < NN) g_h[(n0 + r) * 128 + c] = y;
        }
    }
    __syncthreads();

    // GEMM 64x128 = y(64x128) @ Went(128x128), fp16 k16. warp tile 16x64
    const int m0 = (wid >> 1) * 16;
    const int nw = (wid & 1) * 64;
    float acc[8][4];
    {
        #pragma unroll
        for (int t = 0; t < 8; t++)
            #pragma unroll
            for (int q = 0; q < 4; q++) acc[t][q] = 0.f;

        #pragma unroll
        for (int ks = 0; ks < 8; ks++) {
            int k0 = ks * 16, kh = ks * 8;
            unsigned a0 = *(unsigned*)&yh[(m0 + group) * 132 + k0 + 2 * tig];
            unsigned a1 = *(unsigned*)&yh[(m0 + group + 8) * 132 + k0 + 2 * tig];
            unsigned a2 = *(unsigned*)&yh[(m0 + group) * 132 + k0 + 2 * tig + 8];
            unsigned a3 = *(unsigned*)&yh[(m0 + group + 8) * 132 + k0 + 2 * tig + 8];
            #pragma unroll
            for (int nt = 0; nt < 8; nt++) {
                int c = nw + nt * 8 + group;
                unsigned b0 = g_Wenth[(kh + tig) * 128 + c];
                unsigned b1 = g_Wenth[(kh + tig + 4) * 128 + c];
                mma_f16(acc[nt], a0, a1, a2, a3, b0, b1);
            }
        }
    }

    // epilogue 1: feat -> g_f0h (bf16 only)
    {
        const int r = m0 + group;
        #pragma unroll
        for (int nt = 0; nt < 8; nt++) {
            int cc = nw + nt * 8 + 2 * tig;
            if (n0 + r < NN) {
                *(__nv_bfloat162*)&g_f0h[(n0 + r) * 128 + cc] =
                    __float22bfloat162_rn(make_float2(acc[nt][0], acc[nt][1]));
            }
            if (n0 + r + 8 < NN) {
                *(__nv_bfloat162*)&g_f0h[(n0 + r + 8) * 128 + cc] =
                    __float22bfloat162_rn(make_float2(acc[nt][2], acc[nt][3]));
            }
        }
    }

    // epilogue 2: eh/et from fragments (tig-lane reduce), fp16 stores
    {
        const int r = m0 + group;
        #pragma unroll
        for (int hh = 0; hh < 4; hh++) {
            float seA = 0.f, seB = 0.f, stA = 0.f, stB = 0.f;
            #pragma unroll
            for (int j = 0; j < 2; j++) {
                int nt = 2 * hh + j;
                int cc = nw + nt * 8 + 2 * tig;
                float ah0 = __ldg(&ah[cc]),     ah1 = __ldg(&ah[cc + 1]);
                float at0 = __ldg(&at[cc]),     at1 = __ldg(&at[cc + 1]);
                seA += acc[nt][0] * ah0 + acc[nt][1] * ah1;
                seB += acc[nt][2] * ah0 + acc[nt][3] * ah1;
                stA += acc[nt][0] * at0 + acc[nt][1] * at1;
                stB += acc[nt][2] * at0 + acc[nt][3] * at1;
            }
            #pragma unroll
            for (int o = 1; o < 4; o <<= 1) {
                seA += __shfl_xor_sync(0xffffffffu, seA, o);
                seB += __shfl_xor_sync(0xffffffffu, seB, o);
                stA += __shfl_xor_sync(0xffffffffu, stA, o);
                stB += __shfl_xor_sync(0xffffffffu, stB, o);
            }
            if (tig == 0) {
                int hg = (nw >> 4) + hh;
                if (n0 + r < NN) {
                    g_eh[(n0 + r) * 8 + hg] = __float2half(seA);
                    g_et[(n0 + r) * 8 + hg] = __float2half(stA);
                }
                if (n0 + r + 8 < NN) {
                    g_eh[(n0 + r + 8) * 8 + hg] = __float2half(seB);
                    g_et[(n0 + r + 8) * 8 + hg] = __float2half(stB);
                }
            }
        }
    }
}

// ---------------- K2: er per relation (fp16 store) ---------------------------
__global__ void k_rel(const float* __restrict__ rel,
                      const float* __restrict__ Wrel,
                      const float* __restrict__ ar)
{
    __shared__ float srow[128];
    const int r = blockIdx.x, k = threadIdx.x;
    srow[k] = rel[r * 128 + k];
    __syncthreads();
    float acc = 0.f;
    for (int j = 0; j < 128; j++) acc += srow[j] * Wrel[j * 128 + k];
    float v = acc * ar[k];
    #pragma unroll
    for (int o = 8; o; o >>= 1) v += __shfl_xor_sync(0xffffffffu, v, o);
    if ((k & 15) == 0) g_er[r * 8 + (k >> 4)] = __float2half(v);
}

// ---------------- CSR build -------------------------------------------------
__global__ void k_zero() {
    int i = blockIdx.x * blockDim.x + threadIdx.x;
    if (i < NN) g_deg[i] = 0;
}

__global__ void k_hist(const int* __restrict__ dst) {
    int e = blockIdx.x * blockDim.x + threadIdx.x;
    if (e < EE) atomicAdd(&g_deg[dst[e]], 1);
}

__global__ void __launch_bounds__(SCAN_B) k_scanA() {
    __shared__ int red[SCAN_B / 32];
    const int t = threadIdx.x;
    const int i = blockIdx.x * SCAN_B + t;
    int v = (i < NN) ? g_deg[i] : 0;
    int s = v;
    #pragma unroll
    for (int o = 16; o; o >>= 1) s += __shfl_xor_sync(0xffffffffu, s, o);
    if ((t & 31) == 0) red[t >> 5] = s;
    __syncthreads();
    if (t < 32) {
        int x = (t < SCAN_B / 32) ? red[t] : 0;
        #pragma unroll
        for (int o = 16; o; o >>= 1) x += __shfl_xor_sync(0xffffffffu, x, o);
        if (t == 0) g_part[blockIdx.x] = x;
    }
}

__global__ void __launch_bounds__(512) k_scanB() {
    __shared__ int sp[512];
    const int t = threadIdx.x;
    int v = (t < NBLK) ? g_part[t] : 0;
    sp[t] = v;
    __syncthreads();
    for (int off = 1; off < 512; off <<= 1) {
        int x = (t >= off) ? sp[t - off] : 0;
        __syncthreads();
        sp[t] += x;
        __syncthreads();
    }
    if (t < NBLK) g_part[t] = sp[t] - v;   // exclusive
}

__global__ void __launch_bounds__(SCAN_B) k_scanC() {
    __shared__ int sp[SCAN_B];
    const int t = threadIdx.x;
    const int i = blockIdx.x * SCAN_B + t;
    const int base = g_part[blockIdx.x];
    int v = (i < NN) ? g_deg[i] : 0;
    sp[t] = v;
    __syncthreads();
    for (int off = 1; off < SCAN_B; off <<= 1) {
        int x = (t >= off) ? sp[t - off] : 0;
        __syncthreads();
        sp[t] += x;
        __syncthreads();
    }
    if (i < NN) {
        int excl = base + sp[t] - v;
        g_rowptr[i] = excl;
        g_cursor[i] = excl;
    }
    if (i == NN - 1) g_rowptr[NN] = EE;
}

__global__ void k_scatter(const int* __restrict__ src,
                          const int* __restrict__ dst,
                          const int* __restrict__ etp)
{
    int e = blockIdx.x * blockDim.x + threadIdx.x;
    if (e < EE) {
        int p = atomicAdd(&g_cursor[dst[e]], 1);
        g_srcs[p] = src[e];
        g_ets[p]  = etp[e];
    }
}

// ---------------- K4: edge softmax, SINGLE pass, fp16 in/out -----------------
__global__ void __launch_bounds__(256) k_soft()
{
    const int wid  = (blockIdx.x * blockDim.x + threadIdx.x) >> 5;
    const int lane = threadIdx.x & 31;
    if (wid >= NN) return;
    const int beg = g_rowptr[wid], end = g_rowptr[wid + 1];

    float etn[8];
    unp8(*(const uint4*)&g_et[wid * 8], etn);

    float sm[8];
    #pragma unroll
    for (int h = 0; h < 8; h++) sm[h] = 0.f;

    for (int p = beg + lane; p < end; p += 32) {
        int s = g_srcs[p], t = g_ets[p];
        float eh8[8], er8[8], ex[8];
        unp8(*(const uint4*)&g_eh[s * 8], eh8);
        unp8(*(const uint4*)&g_er[t * 8], er8);
        #pragma unroll
        for (int h = 0; h < 8; h++) {
            float sc = eh8[h] + etn[h] + er8[h];
            sc = sc > 0.f ? sc : SLOPE * sc;
            ex[h] = __expf(sc);
            sm[h] += ex[h];
        }
        uint4 st;
        st.x = packh2(ex[0], ex[1]);
        st.y = packh2(ex[2], ex[3]);
        st.z = packh2(ex[4], ex[5]);
        st.w = packh2(ex[6], ex[7]);
        *(uint4*)&g_a[p * 8] = st;
    }
    #pragma unroll
    for (int o = 16; o; o >>= 1)
        #pragma unroll
        for (int h = 0; h < 8; h++)
            sm[h] += __shfl_xor_sync(0xffffffffu, sm[h], o);

    if (lane == 0) {
        float inv[8];
        #pragma unroll
        for (int h = 0; h < 8; h++) inv[h] = (sm[h] > 0.f) ? (1.f / sm[h]) : 0.f;
        float4 i0 = {inv[0], inv[1], inv[2], inv[3]};
        float4 i1 = {inv[4], inv[5], inv[6], inv[7]};
        ((float4*)&g_inv[wid * 8])[0] = i0;
        ((float4*)&g_inv[wid * 8])[1] = i1;
    }
}

// ---------------- K5: one diffusion hop (warp per node, all-bf16/fp16) ------
__global__ void __launch_bounds__(256) k_hop(int hop)
{
    const __nv_bfloat16* finb =
        (hop == 0) ? g_f0h : ((hop & 1) ? g_hA : g_hB);
    const uint2* fin = (const uint2*)finb;   // 8 bytes = 4 bf16 per lane
    __nv_bfloat16* foutb = (hop & 1) ? g_hB : g_hA;
    const bool last = (hop == HOPS - 1);

    const int wid  = (blockIdx.x * blockDim.x + threadIdx.x) >> 5;
    const int lane = threadIdx.x & 31;
    if (wid >= NN) return;
    const int beg = g_rowptr[wid], end = g_rowptr[wid + 1];
    const int h = lane >> 2;

    const float invh = g_inv[wid * 8 + h];

    float4 acc = {0.f, 0.f, 0.f, 0.f};
    for (int pb = beg; pb < end; pb += 32) {
        int cnt = min(32, end - pb);
        #pragma unroll 8
        for (int q = 0; q < cnt; q++) {
            int s = __ldg(&g_srcs[pb + q]);              // uniform broadcast
            float av = __half2float(__ldg(&g_a[(pb + q) * 8 + h]));
            uint2 v = __ldg(&fin[s * 32 + lane]);
            float2 lo = __bfloat1622float2(*(__nv_bfloat162*)&v.x);
            float2 hi = __bfloat1622float2(*(__nv_bfloat162*)&v.y);
            acc.x += av * lo.x; acc.y += av * lo.y;
            acc.z += av * hi.x; acc.w += av * hi.y;
        }
    }

    const float w = (1.f - ALPHA) * invh;
    uint2 f0v = ((const uint2*)g_f0h)[wid * 32 + lane];
    float2 f0lo = __bfloat1622float2(*(__nv_bfloat162*)&f0v.x);
    float2 f0hi = __bfloat1622float2(*(__nv_bfloat162*)&f0v.y);
    float4 o;
    o.x = w * acc.x + ALPHA * f0lo.x;
    o.y = w * acc.y + ALPHA * f0lo.y;
    o.z = w * acc.z + ALPHA * f0hi.x;
    o.w = w * acc.w + ALPHA * f0hi.y;

    if (last) {
        ((float4*)g_fA)[wid * 32 + lane] = o;
    } else {
        __nv_bfloat162 p0 = __float22bfloat162_rn(make_float2(o.x, o.y));
        __nv_bfloat162 p1 = __float22bfloat162_rn(make_float2(o.z, o.w));
        uint2 st;
        st.x = *(unsigned*)&p0;
        st.y = *(unsigned*)&p1;
        ((uint2*)foutb)[wid * 32 + lane] = st;
    }
}

// ---------------- K6: residual + LN2 + FFN + residual (fp16 tensor core) ----
// 128-row tile, 512 threads (16 warps). rst staged in `out` gmem.
// smem = 128*132*2 + 128*520*2 = 166912 B -> 1 block/SM.
__global__ void __launch_bounds__(512, 1) k_ffn(
    const float* __restrict__ g2, const float* __restrict__ be2,
    const float* __restrict__ bb1, const float* __restrict__ bb2,
    float* __restrict__ out)
{
    extern __shared__ float smem_[];
    __half* yh = (__half*)smem_;                 // 128*132 half
    __half* zh = yh + 128 * 132;                 // 128*520 half
    const int n0 = blockIdx.x * 128;
    const int tid = threadIdx.x;
    const int wid = tid >> 5, lane = tid & 31;
    const int group = lane >> 2, tig = lane & 3;

    // 1. rst = f + h -> out (scratch; final value re-added in epilogue)
    for (int i = tid; i < 128 * 128; i += 512) {
        int r = i >> 7, c = i & 127;
        int gr = n0 + r;
        if (gr < NN) out[gr * 128 + c] = g_fA[gr * 128 + c] + g_h[gr * 128 + c];
    }
    __syncthreads();

    // 2. LN2 over rst -> yh (half). warp wid: rows wid*8..+7 (16*8=128)
    #pragma unroll
    for (int rr = 0; rr < 8; rr++) {
        int r = wid * 8 + rr;
        const float* row = &out[(size_t)min(n0 + r, NN - 1) * 128];
        float x[4];
        float s = 0.f, s2 = 0.f;
        #pragma unroll
        for (int k = 0; k < 4; k++) {
            x[k] = row[lane + 32 * k];
            s += x[k]; s2 += x[k] * x[k];
        }
        #pragma unroll
        for (int o = 16; o; o >>= 1) {
            s  += __shfl_xor_sync(0xffffffffu, s, o);
            s2 += __shfl_xor_sync(0xffffffffu, s2, o);
        }
        float mu  = s * (1.f / 128.f);
        float inv = rsqrtf(s2 * (1.f / 128.f) - mu * mu + LNEPS);
        #pragma unroll
        for (int k = 0; k < 4; k++) {
            int c = lane + 32 * k;
            float y = (x[k] - mu) * inv * g2[c] + be2[c];
            yh[r * 132 + c] = __float2half(y);
        }
    }
    __syncthreads();

    // 3. GEMM1: z(128x512) = relu(y @ W1 + b1). m-grid 4 (32 rows), n-grid 4
    //    (128 cols in two 64-wide phases). warp tile 32x64 per phase.
    {
        const int m0 = (wid >> 2) * 32;
        const int nwbase = (wid & 3) * 128;
        #pragma unroll
        for (int ph = 0; ph < 2; ph++) {
            const int nw = nwbase + ph * 64;
            float acc[2][8][4];
            #pragma unroll
            for (int mt = 0; mt < 2; mt++)
                #pragma unroll
                for (int nt = 0; nt < 8; nt++)
                    #pragma unroll
                    for (int q = 0; q < 4; q++) acc[mt][nt][q] = 0.f;

            #pragma unroll
            for (int ks = 0; ks < 8; ks++) {
                int k0 = ks * 16, kh = ks * 8;
                unsigned a[2][4];
                #pragma unroll
                for (int mt = 0; mt < 2; mt++) {
                    int rb = m0 + mt * 16 + group;
                    a[mt][0] = *(unsigned*)&yh[rb * 132 + k0 + 2 * tig];
                    a[mt][1] = *(unsigned*)&yh[(rb + 8) * 132 + k0 + 2 * tig];
                    a[mt][2] = *(unsigned*)&yh[rb * 132 + k0 + 2 * tig + 8];
                    a[mt][3] = *(unsigned*)&yh[(rb + 8) * 132 + k0 + 2 * tig + 8];
                }
                #pragma unroll
                for (int nt = 0; nt < 8; nt++) {
                    int c = nw + nt * 8 + group;
                    unsigned b0 = g_W1h[(kh + tig) * 512 + c];
                    unsigned b1 = g_W1h[(kh + tig + 4) * 512 + c];
                    mma_f16(acc[0][nt], a[0][0], a[0][1], a[0][2], a[0][3], b0, b1);
                    mma_f16(acc[1][nt], a[1][0], a[1][1], a[1][2], a[1][3], b0, b1);
                }
            }
            #pragma unroll
            for (int mt = 0; mt < 2; mt++)
                #pragma unroll
                for (int nt = 0; nt < 8; nt++) {
                    int r  = m0 + mt * 16 + group;
                    int cc = nw + nt * 8 + 2 * tig;
                    float v0 = fmaxf(acc[mt][nt][0] + bb1[cc], 0.f);
                    float v1 = fmaxf(acc[mt][nt][1] + bb1[cc + 1], 0.f);
                    float v2 = fmaxf(acc[mt][nt][2] + bb1[cc], 0.f);
                    float v3 = fmaxf(acc[mt][nt][3] + bb1[cc + 1], 0.f);
                    *(__half2*)&zh[r * 520 + cc]       = __floats2half2_rn(v0, v1);
                    *(__half2*)&zh[(r + 8) * 520 + cc] = __floats2half2_rn(v2, v3);
                }
        }
    }
    __syncthreads();

    // 4. GEMM2: out(128x128) = z @ W2 + b2 + rst(out). m-grid 8 (16 rows),
    //    n-grid 2 (64 cols). warp tile 16x64.
    {
        const int m0 = (wid >> 1) * 16;
        const int nw = (wid & 1) * 64;
        float acc[8][4];
        #pragma unroll
        for (int nt = 0; nt < 8; nt++)
            #pragma unroll
            for (int q = 0; q < 4; q++) acc[nt][q] = 0.f;

        #pragma unroll 8
        for (int ks = 0; ks < 32; ks++) {
            int k0 = ks * 16, kh = ks * 8;
            unsigned a0 = *(unsigned*)&zh[(m0 + group) * 520 + k0 + 2 * tig];
            unsigned a1 = *(unsigned*)&zh[(m0 + group + 8) * 520 + k0 + 2 * tig];
            unsigned a2 = *(unsigned*)&zh[(m0 + group) * 520 + k0 + 2 * tig + 8];
            unsigned a3 = *(unsigned*)&zh[(m0 + group + 8) * 520 + k0 + 2 * tig + 8];
            #pragma unroll
            for (int nt = 0; nt < 8; nt++) {
                int c = nw + nt * 8 + group;
                unsigned b0 = g_W2h[(kh + tig) * 128 + c];
                unsigned b1 = g_W2h[(kh + tig + 4) * 128 + c];
                mma_f16(acc[nt], a0, a1, a2, a3, b0, b1);
            }
        }
        #pragma unroll
        for (int nt = 0; nt < 8; nt++) {
            int r  = m0 + group;
            int cc = nw + nt * 8 + 2 * tig;
            if (n0 + r < NN) {
                size_t i0 = (size_t)(n0 + r) * 128 + cc;
                out[i0]     = acc[nt][0] + bb2[cc]     + out[i0];
                out[i0 + 1] = acc[nt][1] + bb2[cc + 1] + out[i0 + 1];
            }
            if (n0 + r + 8 < NN) {
                size_t i1 = (size_t)(n0 + r + 8) * 128 + cc;
                out[i1]     = acc[nt][2] + bb2[cc]     + out[i1];
                out[i1 + 1] = acc[nt][3] + bb2[cc + 1] + out[i1 + 1];
            }
        }
    }
}

// ---------------- launch ----------------------------------------------------
extern "C" void kernel_launch(void* const* d_in, const int* in_sizes, int n_in,
                              void* d_out, int out_size)
{
    const float* ent   = (const float*)d_in[0];
    const float* rel   = (const float*)d_in[1];
    const int*   src   = (const int*)  d_in[2];
    const int*   dst   = (const int*)  d_in[3];
    const int*   etp   = (const int*)  d_in[4];
    const float* ln1g  = (const float*)d_in[5];
    const float* ln1b  = (const float*)d_in[6];
    const float* Went  = (const float*)d_in[7];
    const float* Wrel  = (const float*)d_in[8];
    const float* ah    = (const float*)d_in[9];
    const float* at    = (const float*)d_in[10];
    const float* ar    = (const float*)d_in[11];
    const float* ln2g  = (const float*)d_in[12];
    const float* ln2b  = (const float*)d_in[13];
    const float* W1    = (const float*)d_in[14];
    const float* b1    = (const float*)d_in[15];
    const float* W2    = (const float*)d_in[16];
    const float* b2    = (const float*)d_in[17];
    float* out = (float*)d_out;

    static const size_t LN1_SMEM = 64 * 132 * sizeof(__half);                 // 16896
    static const size_t FFN_SMEM = (128 * 132 + 128 * 520) * sizeof(__half);  // 166912
    cudaFuncSetAttribute(k_ln1_feat, cudaFuncAttributeMaxDynamicSharedMemorySize, (int)LN1_SMEM);
    cudaFuncSetAttribute(k_ffn, cudaFuncAttributeMaxDynamicSharedMemorySize, (int)FFN_SMEM);

    // 1-3: weights, deg init, histogram
    k_cvt<<<(CVT_TOTAL + 255) / 256, 256>>>(Went, W1, W2);
    k_zero<<<(NN + 255) / 256, 256>>>();
    k_hist<<<EE / 256, 256>>>(dst);

    // 4: node projection (profiled slot)
    k_ln1_feat<<<(NN + 63) / 64, 256, LN1_SMEM>>>(ent, ln1g, ln1b, ah, at);
    k_rel<<<RR, 128>>>(rel, Wrel, ar);

    // CSR build (parallel scan)
    k_scanA<<<NBLK, SCAN_B>>>();
    k_scanB<<<1, 512>>>();
    k_scanC<<<NBLK, SCAN_B>>>();
    k_scatter<<<EE / 256, 256>>>(src, dst, etp);

    // edge softmax (single pass, fp16 streams)
    k_soft<<<NN / 8, 256>>>();

    // diffusion (bf16 state)
    for (int hop = 0; hop < HOPS; hop++)
        k_hop<<<NN / 8, 256>>>(hop);

    // FFN + residuals (128-row tiles, 512 threads)
    k_ffn<<<(NN + 127) / 128, 512, FFN_SMEM>>>(ln2g, ln2b, b1, b2, out);
}